// round 1
// baseline (speedup 1.0000x reference)
#include <cuda_runtime.h>

#define FF 40
#define DD 768
#define HH 256
#define MAXP 780           // F*(F-1)/2
#define BT_TOTAL (64*256)

// ---------------- device scratch (no allocations allowed) ----------------
__device__ int g_mask_kind;                     // 0=u8, 1=i32, 2=f32
__device__ int g_P;                             // number of available pairs
__device__ unsigned long long g_pairmask[MAXP]; // (1<<i)|(1<<j)
__device__ int g_pi[MAXP];
__device__ int g_pj[MAXP];
__device__ unsigned long long g_availrow[FF];   // bits j>i with avail[i][j]
__device__ float g_EW[MAXP * HH];               // 780*256*4 = 800KB

// ---------------- 0) detect bool serialization ----------------
// Reads the first n_elems/4 32-bit words (safe for all candidate dtypes).
// f32 ones are 0x3F800000; i32 words are 0/1; random u8 0/1 bytes give
// packed words matching neither pattern.
__global__ void detect_kernel(const unsigned int* __restrict__ w, int n_elems) {
    int nw = n_elems >> 2;
    int okF = 1, okI = 1;
    for (int i = threadIdx.x; i < nw; i += blockDim.x) {
        unsigned int v = w[i];
        okF &= (v == 0u) | (v == 0x3F800000u);
        okI &= (v <= 1u);
    }
    okF = __syncthreads_and(okF);
    okI = __syncthreads_and(okI);
    if (threadIdx.x == 0) g_mask_kind = okF ? 2 : (okI ? 1 : 0);
}

__device__ __forceinline__ int mask_at(const void* p, int idx, int kind) {
    if (kind == 0) return ((const unsigned char*)p)[idx] != 0;
    if (kind == 1) return ((const int*)p)[idx] != 0;
    return ((const float*)p)[idx] != 0.0f;
}

// ---------------- 1) build compacted pair list (deterministic) ----------------
__global__ void build_pairs_kernel(const void* __restrict__ avail) {
    __shared__ unsigned char a[FF * FF];
    __shared__ unsigned char flag[MAXP];
    __shared__ short pis[MAXP], pjs[MAXP];
    int kind = g_mask_kind;
    for (int i = threadIdx.x; i < FF * FF; i += blockDim.x)
        a[i] = (unsigned char)mask_at(avail, i, kind);
    __syncthreads();
    int t = threadIdx.x;
    if (t < MAXP) {
        int i = 0, rem = t;
        while (rem >= (FF - 1 - i)) { rem -= (FF - 1 - i); ++i; }
        int j = i + 1 + rem;
        flag[t] = a[i * FF + j];
        pis[t] = (short)i; pjs[t] = (short)j;
    }
    if (t < FF) {
        unsigned long long r = 0ull;
        for (int j = t + 1; j < FF; ++j)
            if (a[t * FF + j]) r |= 1ull << j;
        g_availrow[t] = r;
    }
    __syncthreads();
    if (t < MAXP) {
        int pre = 0;
        for (int q = 0; q < t; ++q) pre += flag[q];
        if (flag[t]) {
            g_pairmask[pre] = (1ull << pis[t]) | (1ull << pjs[t]);
            g_pi[pre] = pis[t];
            g_pj[pre] = pjs[t];
        }
        if (t == MAXP - 1) g_P = pre + flag[t];
    }
}

// ---------------- 2) EW[p,h] = sum_d E[i_p, j_p, d] * W[h, d] ----------------
#define TP 16
#define TH 64
#define KT 32
__global__ void __launch_bounds__(256) ew_kernel(const float* __restrict__ E,
                                                 const float* __restrict__ W) {
    int P = g_P;
    int p0 = blockIdx.x * TP;
    if (p0 >= P) return;
    int h0 = blockIdx.y * TH;

    __shared__ float sE[KT][TP + 2];   // [k][p]
    __shared__ float sW[KT][TH + 2];   // [k][h]
    __shared__ int sbase[TP];

    int t = threadIdx.x;
    if (t < TP) {
        int p = p0 + t;
        sbase[t] = (p < P) ? (g_pi[p] * FF + g_pj[p]) * DD : 0;
    }
    int hx = t & 31;   // h pair index
    int py = t >> 5;   // p pair index (0..7)
    int prow = py * 2, hcol = hx * 2;
    float a00 = 0.f, a01 = 0.f, a10 = 0.f, a11 = 0.f;
    __syncthreads();

    for (int k0 = 0; k0 < DD; k0 += KT) {
        __syncthreads();
        // load E tile (16 x 32), gathered rows
        #pragma unroll
        for (int r = 0; r < 2; ++r) {
            int idx = t + r * 256;        // 0..511
            int pr = idx >> 5, kc = idx & 31;
            float v = 0.f;
            if (p0 + pr < P) v = E[sbase[pr] + k0 + kc];
            sE[kc][pr] = v;
        }
        // load W tile (64 x 32)
        #pragma unroll
        for (int r = 0; r < 8; ++r) {
            int idx = t + r * 256;        // 0..2047
            int hr = idx >> 5, kc = idx & 31;
            sW[kc][hr] = W[(h0 + hr) * DD + k0 + kc];
        }
        __syncthreads();
        #pragma unroll
        for (int k = 0; k < KT; ++k) {
            float e0 = sE[k][prow], e1 = sE[k][prow + 1];
            float w0 = sW[k][hcol], w1 = sW[k][hcol + 1];
            a00 += e0 * w0; a01 += e0 * w1;
            a10 += e1 * w0; a11 += e1 * w1;
        }
    }
    if (p0 + prow < P) {
        float* o = g_EW + (p0 + prow) * HH + h0 + hcol;
        o[0] = a00; o[1] = a01;
    }
    if (p0 + prow + 1 < P) {
        float* o = g_EW + (p0 + prow + 1) * HH + h0 + hcol;
        o[0] = a10; o[1] = a11;
    }
}

// ---------------- 3) main gather-sum + scale + bias ----------------
__device__ __forceinline__ void fadd4(float4& a, const float4 v) {
    a.x += v.x; a.y += v.y; a.z += v.z; a.w += v.w;
}

__global__ void __launch_bounds__(256) main_kernel(const void* __restrict__ mask,
                                                   const float* __restrict__ bias,
                                                   float* __restrict__ out) {
    __shared__ float sEW[32 * HH];                // 32 KB chunk of EW rows
    __shared__ unsigned long long s_pm[32];
    __shared__ unsigned long long s_bits[32];
    __shared__ unsigned long long s_avr[FF];
    __shared__ float s_bias[HH];

    int t = threadIdx.x;
    int kind = g_mask_kind;
    int P = g_P;

    if (t < HH) s_bias[t] = bias[t];
    if (t < FF) s_avr[t] = g_availrow[t];
    if (t < 32) {
        int bt = blockIdx.x * 32 + t;
        unsigned long long b = 0ull;
        if (kind == 0) {
            const unsigned char* mp = (const unsigned char*)mask + (size_t)bt * FF;
            for (int f = 0; f < FF; ++f) if (mp[f]) b |= 1ull << f;
        } else if (kind == 1) {
            const int* mp = (const int*)mask + (size_t)bt * FF;
            for (int f = 0; f < FF; ++f) if (mp[f]) b |= 1ull << f;
        } else {
            const float* mp = (const float*)mask + (size_t)bt * FF;
            for (int f = 0; f < FF; ++f) if (mp[f] != 0.f) b |= 1ull << f;
        }
        s_bits[t] = b;
    }
    __syncthreads();

    int warp = t >> 5, lane = t & 31;
    unsigned long long bits0 = s_bits[warp * 4 + 0];
    unsigned long long bits1 = s_bits[warp * 4 + 1];
    unsigned long long bits2 = s_bits[warp * 4 + 2];
    unsigned long long bits3 = s_bits[warp * 4 + 3];

    float4 z = make_float4(0.f, 0.f, 0.f, 0.f);
    float4 a00 = z, a01 = z, a10 = z, a11 = z, a20 = z, a21 = z, a30 = z, a31 = z;

    const float4* gEW4 = (const float4*)g_EW;
    float4* sEW4 = (float4*)sEW;
    int nch = (P + 31) >> 5;

    for (int c = 0; c < nch; ++c) {
        __syncthreads();
        int p0 = c * 32;
        #pragma unroll
        for (int r = 0; r < 8; ++r) {
            int idx = t + r * 256;            // 0..2047 float4 slots
            int row = idx >> 6, col = idx & 63;
            if (p0 + row < P) sEW4[idx] = gEW4[(size_t)(p0 + row) * 64 + col];
        }
        if (t < 32) s_pm[t] = (p0 + t < P) ? g_pairmask[p0 + t] : ~0ull;
        __syncthreads();

        for (int p = 0; p < 32; ++p) {
            unsigned long long pm = s_pm[p];
            bool b0 = (bits0 & pm) == pm;
            bool b1 = (bits1 & pm) == pm;
            bool b2 = (bits2 & pm) == pm;
            bool b3 = (bits3 & pm) == pm;
            if (!(b0 | b1 | b2 | b3)) continue;
            float4 v0 = sEW4[p * 64 + lane];
            float4 v1 = sEW4[p * 64 + 32 + lane];
            if (b0) { fadd4(a00, v0); fadd4(a01, v1); }
            if (b1) { fadd4(a10, v0); fadd4(a11, v1); }
            if (b2) { fadd4(a20, v0); fadd4(a21, v1); }
            if (b3) { fadd4(a30, v0); fadd4(a31, v1); }
        }
    }

    // epilogue: cnt, scale, bias, store
    float4 bb0 = ((const float4*)s_bias)[lane];
    float4 bb1 = ((const float4*)s_bias)[32 + lane];
    unsigned long long rb[4] = { bits0, bits1, bits2, bits3 };
    float4 ac[4][2] = { {a00, a01}, {a10, a11}, {a20, a21}, {a30, a31} };

    int btbase = blockIdx.x * 32 + warp * 4;
    #pragma unroll
    for (int r = 0; r < 4; ++r) {
        unsigned long long bits = rb[r];
        int cnt = 0;
        unsigned long long b = bits;
        while (b) {
            int i = __ffsll((long long)b) - 1;
            b &= b - 1;
            cnt += __popcll(s_avr[i] & bits);
        }
        float scale = (cnt > 0) ? (1.0f / (float)cnt) : 0.0f;
        float4 o0, o1;
        o0.x = ac[r][0].x * scale + bb0.x;
        o0.y = ac[r][0].y * scale + bb0.y;
        o0.z = ac[r][0].z * scale + bb0.z;
        o0.w = ac[r][0].w * scale + bb0.w;
        o1.x = ac[r][1].x * scale + bb1.x;
        o1.y = ac[r][1].y * scale + bb1.y;
        o1.z = ac[r][1].z * scale + bb1.z;
        o1.w = ac[r][1].w * scale + bb1.w;
        float4* op = (float4*)(out + (size_t)(btbase + r) * HH);
        op[lane] = o0;
        op[32 + lane] = o1;
    }
}

// ---------------- launch ----------------
extern "C" void kernel_launch(void* const* d_in, const int* in_sizes, int n_in,
                              void* d_out, int out_size) {
    const void* mask = d_in[0];                    // [64,256,40] bool
    const float* E = (const float*)d_in[1];        // [40,40,768] f32
    const void* avail = (const void*)d_in[2];      // [40,40] bool
    const float* W = (const float*)d_in[3];        // [256,768] f32
    const float* bias = (const float*)d_in[4];     // [256] f32
    float* out = (float*)d_out;                    // [64,256,256] f32

    detect_kernel<<<1, 1024>>>((const unsigned int*)mask, in_sizes[0]);
    build_pairs_kernel<<<1, 1024>>>(avail);
    ew_kernel<<<dim3((MAXP + TP - 1) / TP, HH / TH), 256>>>(E, W);
    main_kernel<<<BT_TOTAL / 32, 256>>>(mask, bias, out);
}

// round 3
// speedup vs baseline: 1.9983x; 1.9983x over previous
#include <cuda_runtime.h>
#include <cuda_bf16.h>
#include <cstdint>

#define FF 40
#define DD 768
#define HH 256
#define MAXP 780           // F*(F-1)/2
#define PPAD 832           // 13*64, >= MAXP, multiple of 64
#define BT_TOTAL (64*256)
#define KC 64

// ---------------- device scratch (no allocations allowed) ----------------
__device__ int g_mask_kind;                     // 0=u8, 1=i32, 2=f32
__device__ int g_P;                             // number of available pairs
__device__ unsigned long long g_pairmask[PPAD]; // (1<<i)|(1<<j); pad = ~0 (never matches)
__device__ int g_pi[MAXP];
__device__ int g_pj[MAXP];
__device__ unsigned long long g_availrow[FF];   // bits j>i with avail[i][j]
__device__ unsigned long long g_bits[BT_TOTAL];
__device__ float g_scale[BT_TOTAL];
__device__ __nv_bfloat16 g_EWThi[HH * PPAD];    // transposed: [h][p]
__device__ __nv_bfloat16 g_EWTlo[HH * PPAD];

__device__ __forceinline__ uint32_t smem_u32(const void* p) {
    return (uint32_t)__cvta_generic_to_shared(p);
}

// ---------------- 0) detect bool serialization ----------------
__global__ void detect_kernel(const unsigned int* __restrict__ w, int n_elems) {
    int nw = n_elems >> 2;
    if (nw > 16384) nw = 16384;
    int okF = 1, okI = 1;
    for (int i = threadIdx.x; i < nw; i += blockDim.x) {
        unsigned int v = w[i];
        okF &= (v == 0u) | (v == 0x3F800000u);
        okI &= (v <= 1u);
    }
    okF = __syncthreads_and(okF);
    okI = __syncthreads_and(okI);
    if (threadIdx.x == 0) g_mask_kind = okF ? 2 : (okI ? 1 : 0);
}

__device__ __forceinline__ int mask_at(const void* p, int idx, int kind) {
    if (kind == 0) return ((const unsigned char*)p)[idx] != 0;
    if (kind == 1) return ((const int*)p)[idx] != 0;
    return ((const float*)p)[idx] != 0.0f;
}

// ---------------- 1) build compacted pair list (deterministic) ----------------
__global__ void build_pairs_kernel(const void* __restrict__ avail) {
    __shared__ unsigned char a[FF * FF];
    __shared__ unsigned char flag[MAXP];
    __shared__ short pis[MAXP], pjs[MAXP];
    __shared__ int s_P;
    int kind = g_mask_kind;
    for (int i = threadIdx.x; i < FF * FF; i += blockDim.x)
        a[i] = (unsigned char)mask_at(avail, i, kind);
    __syncthreads();
    int t = threadIdx.x;
    if (t < MAXP) {
        int i = 0, rem = t;
        while (rem >= (FF - 1 - i)) { rem -= (FF - 1 - i); ++i; }
        int j = i + 1 + rem;
        flag[t] = a[i * FF + j];
        pis[t] = (short)i; pjs[t] = (short)j;
    }
    if (t < FF) {
        unsigned long long r = 0ull;
        for (int j = t + 1; j < FF; ++j)
            if (a[t * FF + j]) r |= 1ull << j;
        g_availrow[t] = r;
    }
    __syncthreads();
    if (t < MAXP) {
        int pre = 0;
        for (int q = 0; q < t; ++q) pre += flag[q];
        if (flag[t]) {
            g_pairmask[pre] = (1ull << pis[t]) | (1ull << pjs[t]);
            g_pi[pre] = pis[t];
            g_pj[pre] = pjs[t];
        }
        if (t == MAXP - 1) { g_P = pre + flag[t]; s_P = pre + flag[t]; }
    }
    __syncthreads();
    int P = s_P;
    if (t < PPAD && t >= P) g_pairmask[t] = ~0ull;   // pad: never matches (bits < 2^40)
}

// ---------------- 2) EWT[h,p] = sum_d E[i_p,j_p,d] * W[h,d], bf16 hi/lo split ----------------
#define TP 16
#define TH 64
#define KT 32
__global__ void __launch_bounds__(256) ew_kernel(const float* __restrict__ E,
                                                 const float* __restrict__ W) {
    int P = g_P;
    int p0 = blockIdx.x * TP;
    int h0 = blockIdx.y * TH;

    __shared__ float sE[KT][TP + 2];
    __shared__ float sW[KT][TH + 2];
    __shared__ int sbase[TP];

    int t = threadIdx.x;
    if (t < TP) {
        int p = p0 + t;
        sbase[t] = (p < P) ? (g_pi[p] * FF + g_pj[p]) * DD : 0;
    }
    int hx = t & 31;
    int py = t >> 5;
    int prow = py * 2, hcol = hx * 2;
    float a00 = 0.f, a01 = 0.f, a10 = 0.f, a11 = 0.f;
    __syncthreads();

    for (int k0 = 0; k0 < DD; k0 += KT) {
        __syncthreads();
        #pragma unroll
        for (int r = 0; r < 2; ++r) {
            int idx = t + r * 256;
            int pr = idx >> 5, kc = idx & 31;
            float v = 0.f;
            if (p0 + pr < P) v = E[sbase[pr] + k0 + kc];
            sE[kc][pr] = v;
        }
        #pragma unroll
        for (int r = 0; r < 8; ++r) {
            int idx = t + r * 256;
            int hr = idx >> 5, kc = idx & 31;
            sW[kc][hr] = W[(h0 + hr) * DD + k0 + kc];
        }
        __syncthreads();
        #pragma unroll
        for (int k = 0; k < KT; ++k) {
            float e0 = sE[k][prow], e1 = sE[k][prow + 1];
            float w0 = sW[k][hcol], w1 = sW[k][hcol + 1];
            a00 += e0 * w0; a01 += e0 * w1;
            a10 += e1 * w0; a11 += e1 * w1;
        }
    }
    // p >= P rows are exact zeros (sE forced 0), so padding region is zero-filled
    float vals[4] = {a00, a01, a10, a11};
    #pragma unroll
    for (int q = 0; q < 4; ++q) {
        int p = p0 + prow + (q >> 1);
        int h = h0 + hcol + (q & 1);
        float v = vals[q];
        __nv_bfloat16 hi = __float2bfloat16(v);
        __nv_bfloat16 lo = __float2bfloat16(v - __bfloat162float(hi));
        g_EWThi[h * PPAD + p] = hi;
        g_EWTlo[h * PPAD + p] = lo;
    }
}

// ---------------- 3) per-bt bitmask + 1/cnt ----------------
__global__ void prep_kernel(const void* __restrict__ mask) {
    __shared__ unsigned long long s_avr[FF];
    int t = threadIdx.x;
    if (t < FF) s_avr[t] = g_availrow[t];
    __syncthreads();
    int bt = blockIdx.x * 256 + t;
    int kind = g_mask_kind;
    unsigned long long b = 0ull;
    if (kind == 0) {
        const unsigned char* mp = (const unsigned char*)mask + (size_t)bt * FF;
        for (int f = 0; f < FF; ++f) if (mp[f]) b |= 1ull << f;
    } else if (kind == 1) {
        const int* mp = (const int*)mask + (size_t)bt * FF;
        for (int f = 0; f < FF; ++f) if (mp[f]) b |= 1ull << f;
    } else {
        const float* mp = (const float*)mask + (size_t)bt * FF;
        for (int f = 0; f < FF; ++f) if (mp[f] != 0.f) b |= 1ull << f;
    }
    int cnt = 0;
    unsigned long long x = b;
    while (x) {
        int i = __ffsll((long long)x) - 1;
        x &= x - 1;
        cnt += __popcll(s_avr[i] & b);
    }
    g_bits[bt] = b;
    g_scale[bt] = (cnt > 0) ? (1.0f / (float)cnt) : 0.0f;
}

// ---------------- 4) mma.sync GEMM: out = (sel @ [EWhi + EWlo]) * scale + bias ----------------
// BM=128, BN=128, KC=64 pairs/chunk; 8 warps (4 m x 2 n); warp tile 32x64.
// A (sel) built in smem from bitmasks; B (hi+lo) via cp.async, double buffered.
#define ABYTES  (128 * 128)              // 128 rows x 64 bf16 (128B)
#define BBYTES  (128 * 128)              // per matrix
#define BUFBYTES (ABYTES + 2 * BBYTES)   // 48 KB
#define DSMEM_BYTES (2 * BUFBYTES + 128)

#define LDSM4(r0, r1, r2, r3, addr) \
    asm volatile("ldmatrix.sync.aligned.m8n8.x4.shared.b16 {%0,%1,%2,%3}, [%4];" \
                 : "=r"(r0), "=r"(r1), "=r"(r2), "=r"(r3) : "r"(addr))

#define MMA_BF16(d, a, b0v, b1v) \
    asm volatile("mma.sync.aligned.m16n8k16.row.col.f32.bf16.bf16.f32 " \
                 "{%0,%1,%2,%3}, {%4,%5,%6,%7}, {%8,%9}, {%0,%1,%2,%3};" \
                 : "+f"((d)[0]), "+f"((d)[1]), "+f"((d)[2]), "+f"((d)[3]) \
                 : "r"((a)[0]), "r"((a)[1]), "r"((a)[2]), "r"((a)[3]), \
                   "r"(b0v), "r"(b1v))

__global__ void __launch_bounds__(256, 1)
gemm_kernel(const float* __restrict__ bias, float* __restrict__ out) {
    extern __shared__ char dyn_raw[];
    __shared__ unsigned long long s_pm[PPAD];
    __shared__ unsigned long long s_bits[128];
    __shared__ float s_bias[128];

    uint32_t raw = smem_u32(dyn_raw);
    uint32_t base = (raw + 127u) & ~127u;
    uint32_t buf0 = base, buf1 = base + BUFBYTES;

    const int t = threadIdx.x;
    const int lane = t & 31, wid = t >> 5;
    const int wm = (wid & 3) * 32;
    const int wn = (wid >> 2) * 64;
    const int m0 = blockIdx.x * 128;
    const int n0 = blockIdx.y * 128;

    for (int i = t; i < PPAD; i += 256) s_pm[i] = g_pairmask[i];
    if (t < 128) { s_bits[t] = g_bits[m0 + t]; s_bias[t] = bias[n0 + t]; }
    __syncthreads();

    int P = g_P;
    int nch = (P + KC - 1) / KC;
    if (nch < 1) nch = 1;

    // ---- B chunk via cp.async (hi + lo), swizzled 16B units ----
    #define ISSUE_B(c, bufbase) do {                                               \
        _Pragma("unroll")                                                          \
        for (int r = 0; r < 8; ++r) {                                              \
            int idx = t + r * 256;                                                 \
            int half = idx >> 10;                                                  \
            int u = idx & 1023;                                                    \
            int row = u >> 3, kc = u & 7;                                          \
            const __nv_bfloat16* src =                                             \
                (half ? g_EWTlo : g_EWThi) +                                       \
                (size_t)(n0 + row) * PPAD + (c) * KC + kc * 8;                     \
            uint32_t dst = (bufbase) + ABYTES + half * BBYTES +                    \
                           row * 128 + ((kc ^ (row & 7)) << 4);                    \
            asm volatile("cp.async.cg.shared.global [%0], [%1], 16;"               \
                         :: "r"(dst), "l"(src));                                   \
        }                                                                          \
        asm volatile("cp.async.commit_group;" ::: "memory");                       \
    } while (0)

    // ---- A (sel) chunk built from bitmasks ----
    #define BUILD_A(c, bufbase) do {                                               \
        _Pragma("unroll")                                                          \
        for (int r = 0; r < 4; ++r) {                                              \
            int idx = t + r * 256;                                                 \
            int m = idx >> 3, kc = idx & 7;                                        \
            unsigned long long bb = s_bits[m];                                     \
            int pb = (c) * KC + kc * 8;                                            \
            uint32_t w0, w1, w2, w3;                                               \
            {                                                                      \
                unsigned long long q0 = s_pm[pb+0], q1 = s_pm[pb+1];               \
                w0 = (((bb & q0) == q0) ? 0x3F80u : 0u) |                          \
                     (((bb & q1) == q1) ? 0x3F800000u : 0u);                       \
                unsigned long long q2 = s_pm[pb+2], q3 = s_pm[pb+3];               \
                w1 = (((bb & q2) == q2) ? 0x3F80u : 0u) |                          \
                     (((bb & q3) == q3) ? 0x3F800000u : 0u);                       \
                unsigned long long q4 = s_pm[pb+4], q5 = s_pm[pb+5];               \
                w2 = (((bb & q4) == q4) ? 0x3F80u : 0u) |                          \
                     (((bb & q5) == q5) ? 0x3F800000u : 0u);                       \
                unsigned long long q6 = s_pm[pb+6], q7 = s_pm[pb+7];               \
                w3 = (((bb & q6) == q6) ? 0x3F80u : 0u) |                          \
                     (((bb & q7) == q7) ? 0x3F800000u : 0u);                       \
            }                                                                      \
            uint32_t dst = (bufbase) + m * 128 + ((kc ^ (m & 7)) << 4);            \
            asm volatile("st.shared.v4.b32 [%0], {%1,%2,%3,%4};"                   \
                         :: "r"(dst), "r"(w0), "r"(w1), "r"(w2), "r"(w3));         \
        }                                                                          \
    } while (0)

    float acc[2][8][4];
    #pragma unroll
    for (int i = 0; i < 2; ++i)
        #pragma unroll
        for (int j = 0; j < 8; ++j)
            #pragma unroll
            for (int q = 0; q < 4; ++q) acc[i][j][q] = 0.f;

    ISSUE_B(0, buf0);
    BUILD_A(0, buf0);
    asm volatile("cp.async.wait_group 0;" ::: "memory");
    __syncthreads();

    for (int c = 0; c < nch; ++c) {
        uint32_t cur = (c & 1) ? buf1 : buf0;
        if (c + 1 < nch) {
            uint32_t nxt = (c & 1) ? buf0 : buf1;
            ISSUE_B(c + 1, nxt);
            BUILD_A(c + 1, nxt);
        }
        uint32_t Ab = cur, Bh = cur + ABYTES, Bl = cur + ABYTES + BBYTES;
        #pragma unroll
        for (int ks = 0; ks < 4; ++ks) {
            uint32_t a[2][4];
            #pragma unroll
            for (int mi = 0; mi < 2; ++mi) {
                int arow = wm + mi * 16 + (lane & 7) + ((lane >> 3) & 1) * 8;
                int akc = ks * 2 + (lane >> 4);
                uint32_t ad = Ab + arow * 128 + ((akc ^ (arow & 7)) << 4);
                LDSM4(a[mi][0], a[mi][1], a[mi][2], a[mi][3], ad);
            }
            #pragma unroll
            for (int nb2 = 0; nb2 < 4; ++nb2) {
                int brow = wn + nb2 * 16 + (lane & 7) + (lane >> 4) * 8;
                int bkc = ks * 2 + ((lane >> 3) & 1);
                uint32_t off = brow * 128 + ((bkc ^ (brow & 7)) << 4);
                uint32_t h0, h1, h2, h3, l0, l1, l2, l3;
                LDSM4(h0, h1, h2, h3, Bh + off);
                LDSM4(l0, l1, l2, l3, Bl + off);
                MMA_BF16(acc[0][nb2 * 2 + 0], a[0], h0, h1);
                MMA_BF16(acc[1][nb2 * 2 + 0], a[1], h0, h1);
                MMA_BF16(acc[0][nb2 * 2 + 1], a[0], h2, h3);
                MMA_BF16(acc[1][nb2 * 2 + 1], a[1], h2, h3);
                MMA_BF16(acc[0][nb2 * 2 + 0], a[0], l0, l1);
                MMA_BF16(acc[1][nb2 * 2 + 0], a[1], l0, l1);
                MMA_BF16(acc[0][nb2 * 2 + 1], a[0], l2, l3);
                MMA_BF16(acc[1][nb2 * 2 + 1], a[1], l2, l3);
            }
        }
        if (c + 1 < nch) {
            asm volatile("cp.async.wait_group 0;" ::: "memory");
        }
        __syncthreads();
    }

    // ---- epilogue: scale by 1/cnt, add bias, store ----
    #pragma unroll
    for (int mi = 0; mi < 2; ++mi) {
        int row0 = m0 + wm + mi * 16 + (lane >> 2);
        float sc0 = g_scale[row0];
        float sc1 = g_scale[row0 + 8];
        #pragma unroll
        for (int ni = 0; ni < 8; ++ni) {
            int col = wn + ni * 8 + 2 * (lane & 3);
            float bv0 = s_bias[col], bv1 = s_bias[col + 1];
            float2 o0, o1;
            o0.x = acc[mi][ni][0] * sc0 + bv0;
            o0.y = acc[mi][ni][1] * sc0 + bv1;
            o1.x = acc[mi][ni][2] * sc1 + bv0;
            o1.y = acc[mi][ni][3] * sc1 + bv1;
            *(float2*)(out + (size_t)row0 * HH + n0 + col) = o0;
            *(float2*)(out + (size_t)(row0 + 8) * HH + n0 + col) = o1;
        }
    }
}

// ---------------- launch ----------------
extern "C" void kernel_launch(void* const* d_in, const int* in_sizes, int n_in,
                              void* d_out, int out_size) {
    const void* mask = d_in[0];                    // [64,256,40] bool
    const float* E = (const float*)d_in[1];        // [40,40,768] f32
    const void* avail = (const void*)d_in[2];      // [40,40] bool
    const float* W = (const float*)d_in[3];        // [256,768] f32
    const float* bias = (const float*)d_in[4];     // [256] f32
    float* out = (float*)d_out;                    // [64,256,256] f32

    cudaFuncSetAttribute(gemm_kernel, cudaFuncAttributeMaxDynamicSharedMemorySize,
                         DSMEM_BYTES);

    detect_kernel<<<1, 1024>>>((const unsigned int*)mask, in_sizes[0]);
    build_pairs_kernel<<<1, 1024>>>(avail);
    ew_kernel<<<dim3(PPAD / TP, HH / TH), 256>>>(E, W);
    prep_kernel<<<BT_TOTAL / 256, 256>>>(mask);
    gemm_kernel<<<dim3(BT_TOTAL / 128, 2), 256, DSMEM_BYTES>>>(bias, out);
}

// round 4
// speedup vs baseline: 2.8294x; 1.4159x over previous
#include <cuda_runtime.h>
#include <cuda_fp16.h>
#include <cstdint>

#define FF 40
#define DD 768
#define HH 256
#define MAXP 780           // F*(F-1)/2
#define PPAD 832           // 13*64, >= MAXP, multiple of 64
#define BT_TOTAL (64*256)
#define KC 64

// ---------------- device scratch (no allocations allowed) ----------------
__device__ int g_mask_kind;                     // 0=u8, 1=32-bit (i32/f32)
__device__ int g_P;
__device__ unsigned long long g_pairmask[PPAD]; // (1<<i)|(1<<j); pad = ~0 (never matches)
__device__ int g_pi[MAXP];
__device__ int g_pj[MAXP];
__device__ unsigned long long g_availrow[FF];
__device__ __align__(16) __half g_EWT[HH * PPAD];  // transposed: [h][p], fp16

__device__ __forceinline__ uint32_t smem_u32(const void* p) {
    return (uint32_t)__cvta_generic_to_shared(p);
}

// ---------------- 1) setup: detect dtype + build compacted pair list ----------------
// i32 and f32 bools both satisfy "word != 0 == true", so we only need to
// distinguish u8 (packed bytes) from 32-bit element serialization.
__global__ void __launch_bounds__(1024) setup_kernel(const unsigned int* __restrict__ mask_w,
                                                     int n_elems,
                                                     const void* __restrict__ avail) {
    __shared__ unsigned char a[FF * FF];
    __shared__ int s_wexc[32];
    __shared__ int s_wcnt[32];
    __shared__ int s_kind, s_P;

    int t = threadIdx.x;
    int lane = t & 31, warp = t >> 5;

    // detect: u8 bool data packs 0/1 bytes into words that are neither 0/1
    // nor valid patterns of 32-bit bool elements.
    {
        int nw = n_elems >> 2;
        if (nw > 8192) nw = 8192;
        int ok32 = 1;  // every word is 0, 1, or 0x3F800000 (i32/f32 bools)
        for (int i = t; i < nw; i += 1024) {
            unsigned int v = mask_w[i];
            ok32 &= (v == 0u) | (v == 1u) | (v == 0x3F800000u);
        }
        ok32 = __syncthreads_and(ok32);
        if (t == 0) { s_kind = ok32 ? 1 : 0; g_mask_kind = ok32 ? 1 : 0; }
    }
    __syncthreads();
    int kind = s_kind;

    for (int i = t; i < FF * FF; i += 1024) {
        int v;
        if (kind == 0) v = ((const unsigned char*)avail)[i] != 0;
        else           v = ((const unsigned int*)avail)[i] != 0;
        a[i] = (unsigned char)v;
    }
    __syncthreads();

    if (t < FF) {
        unsigned long long r = 0ull;
        for (int j = t + 1; j < FF; ++j)
            if (a[t * FF + j]) r |= 1ull << j;
        g_availrow[t] = r;
    }

    // flags + ballot-based compaction
    int flag = 0, pi = 0, pj = 0;
    if (t < MAXP) {
        int i = 0, rem = t;
        while (rem >= (FF - 1 - i)) { rem -= (FF - 1 - i); ++i; }
        int j = i + 1 + rem;
        flag = a[i * FF + j];
        pi = i; pj = j;
    }
    unsigned int bal = __ballot_sync(0xffffffffu, flag);
    if (lane == 0) s_wcnt[warp] = __popc(bal);
    __syncthreads();
    if (t == 0) {
        int s = 0;
        for (int w = 0; w < 32; ++w) { s_wexc[w] = s; s += s_wcnt[w]; }
        s_P = s; g_P = s;
    }
    __syncthreads();
    if (flag) {
        int pre = s_wexc[warp] + __popc(bal & ((1u << lane) - 1u));
        g_pairmask[pre] = (1ull << pi) | (1ull << pj);
        g_pi[pre] = pi;
        g_pj[pre] = pj;
    }
    int P = s_P;
    if (t < PPAD && t >= P) g_pairmask[t] = ~0ull;
}

// ---------------- 2) EWT[h,p] = sum_d E[i_p,j_p,d] * W[h,d]  (fp32 -> fp16) ----------------
// grid (52, 4): 16 p-rows x 64 h-cols per block; 2p x 2h microtile (h strided 32).
__global__ void __launch_bounds__(256) ew_kernel(const float* __restrict__ E,
                                                 const float* __restrict__ W) {
    int P = g_P;
    int p0 = blockIdx.x * 16;
    int h0 = blockIdx.y * 64;
    int t = threadIdx.x;

    if (p0 >= P) {  // pure padding: zero-fill and leave
        for (int idx = t; idx < 16 * 64; idx += 256) {
            int pr = idx & 15, hc = idx >> 4;
            g_EWT[(h0 + hc) * PPAD + p0 + pr] = __float2half_rn(0.f);
        }
        return;
    }

    __shared__ float sE[16][36];   // [p][k], pitch 36 (144B, 16B aligned rows)
    __shared__ float sW[64][36];   // [h][k]
    __shared__ int sbase[16];

    if (t < 16) {
        int p = p0 + t;
        sbase[t] = (p < P) ? (g_pi[p] * FF + g_pj[p]) * DD : -1;
    }
    int prow = (t >> 5) * 2;       // warp-uniform
    int hc = t & 31;
    float a00 = 0.f, a01 = 0.f, a10 = 0.f, a11 = 0.f;
    __syncthreads();

    for (int k0 = 0; k0 < DD; k0 += 32) {
        __syncthreads();
        if (t < 128) {             // E tile: 16 x 32 = 128 float4
            int row = t >> 3, kq = t & 7;
            int b = sbase[row];
            float4 v = make_float4(0.f, 0.f, 0.f, 0.f);
            if (b >= 0) v = *(const float4*)(E + b + k0 + kq * 4);
            *(float4*)&sE[row][kq * 4] = v;
        }
        #pragma unroll
        for (int r = 0; r < 2; ++r) { // W tile: 64 x 32 = 512 float4
            int idx = t + r * 256;
            int row = idx >> 3, kq = idx & 7;
            *(float4*)&sW[row][kq * 4] =
                *(const float4*)(W + (size_t)(h0 + row) * DD + k0 + kq * 4);
        }
        __syncthreads();
        #pragma unroll
        for (int kk = 0; kk < 32; kk += 4) {
            float4 e0 = *(float4*)&sE[prow][kk];
            float4 e1 = *(float4*)&sE[prow + 1][kk];
            float4 w0 = *(float4*)&sW[hc][kk];
            float4 w1 = *(float4*)&sW[hc + 32][kk];
            a00 += e0.x * w0.x + e0.y * w0.y + e0.z * w0.z + e0.w * w0.w;
            a01 += e0.x * w1.x + e0.y * w1.y + e0.z * w1.z + e0.w * w1.w;
            a10 += e1.x * w0.x + e1.y * w0.y + e1.z * w0.z + e1.w * w0.w;
            a11 += e1.x * w1.x + e1.y * w1.y + e1.z * w1.z + e1.w * w1.w;
        }
    }
    int pA = p0 + prow, pB = pA + 1;
    g_EWT[(h0 + hc) * PPAD + pA]      = __float2half_rn(a00);
    g_EWT[(h0 + hc + 32) * PPAD + pA] = __float2half_rn(a01);
    g_EWT[(h0 + hc) * PPAD + pB]      = __float2half_rn(a10);
    g_EWT[(h0 + hc + 32) * PPAD + pB] = __float2half_rn(a11);
}

// ---------------- 3) mma.sync GEMM: out = (sel @ EW) * (1/cnt) + bias ----------------
// BM=128, BN=256 (full H), KC=64 pairs/chunk; 8 warps (4m x 2n); warp 32m x 128n.
// Integrated per-row bitmask + 1/cnt computation (no separate prep kernel).
#define ABYTES 16384                 // 128 x 64 fp16
#define BBYTES 32768                 // 256 x 64 fp16
#define BUFB (ABYTES + BBYTES)       // 48 KB
#define DSMEM_BYTES (2 * BUFB + 128)

#define LDSM4(r0, r1, r2, r3, addr) \
    asm volatile("ldmatrix.sync.aligned.m8n8.x4.shared.b16 {%0,%1,%2,%3}, [%4];" \
                 : "=r"(r0), "=r"(r1), "=r"(r2), "=r"(r3) : "r"(addr))

#define MMA_F16(d, a, b0v, b1v) \
    asm volatile("mma.sync.aligned.m16n8k16.row.col.f32.f16.f16.f32 " \
                 "{%0,%1,%2,%3}, {%4,%5,%6,%7}, {%8,%9}, {%0,%1,%2,%3};" \
                 : "+f"((d)[0]), "+f"((d)[1]), "+f"((d)[2]), "+f"((d)[3]) \
                 : "r"((a)[0]), "r"((a)[1]), "r"((a)[2]), "r"((a)[3]), \
                   "r"(b0v), "r"(b1v))

__global__ void __launch_bounds__(256, 1)
gemm_kernel(const unsigned int* __restrict__ mask_w,
            const float* __restrict__ bias, float* __restrict__ out) {
    extern __shared__ char dyn_raw[];
    __shared__ unsigned long long s_pm[PPAD];
    __shared__ unsigned long long s_bits[128];
    __shared__ unsigned long long s_avr[FF];
    __shared__ float s_scale[128];
    __shared__ float s_bias[HH];

    uint32_t raw = smem_u32(dyn_raw);
    uint32_t base = (raw + 127u) & ~127u;
    char* dynp = dyn_raw + (base - raw);

    const int t = threadIdx.x;
    const int lane = t & 31, wid = t >> 5;
    const int wm = (wid & 3) * 32;
    const int wn = (wid >> 2) * 128;
    const int m0 = blockIdx.x * 128;

    for (int i = t; i < PPAD; i += 256) s_pm[i] = g_pairmask[i];
    if (t < FF) s_avr[t] = g_availrow[t];
    s_bias[t] = bias[t];
    int kind = g_mask_kind;
    int P = g_P;
    int nch = (P + KC - 1) / KC;
    if (nch < 1) nch = 1;
    __syncthreads();

    // ---- B chunk via cp.async (fp16), swizzled 16B units ----
    #define ISSUE_B(c, bufbase) do {                                               \
        _Pragma("unroll")                                                          \
        for (int r = 0; r < 8; ++r) {                                              \
            int idx = t + r * 256;                                                 \
            int row = idx >> 3, kc = idx & 7;                                      \
            const __half* src = g_EWT + (size_t)row * PPAD + (c) * KC + kc * 8;    \
            uint32_t dst = (bufbase) + ABYTES + row * 128 + ((kc ^ (row & 7)) << 4); \
            asm volatile("cp.async.cg.shared.global [%0], [%1], 16;"               \
                         :: "r"(dst), "l"(src));                                   \
        }                                                                          \
        asm volatile("cp.async.commit_group;" ::: "memory");                       \
    } while (0)

    // ---- A (sel, fp16 1.0 = 0x3C00) built from bitmasks ----
    #define BUILD_A(c, bufbase) do {                                               \
        _Pragma("unroll")                                                          \
        for (int r = 0; r < 4; ++r) {                                              \
            int idx = t + r * 256;                                                 \
            int m = idx >> 3, kc = idx & 7;                                        \
            unsigned long long bb = s_bits[m];                                     \
            int pb = (c) * KC + kc * 8;                                            \
            unsigned long long q0 = s_pm[pb+0], q1 = s_pm[pb+1];                   \
            unsigned long long q2 = s_pm[pb+2], q3 = s_pm[pb+3];                   \
            unsigned long long q4 = s_pm[pb+4], q5 = s_pm[pb+5];                   \
            unsigned long long q6 = s_pm[pb+6], q7 = s_pm[pb+7];                   \
            uint32_t w0 = (((bb & q0) == q0) ? 0x3C00u : 0u) |                     \
                          (((bb & q1) == q1) ? 0x3C000000u : 0u);                  \
            uint32_t w1 = (((bb & q2) == q2) ? 0x3C00u : 0u) |                     \
                          (((bb & q3) == q3) ? 0x3C000000u : 0u);                  \
            uint32_t w2 = (((bb & q4) == q4) ? 0x3C00u : 0u) |                     \
                          (((bb & q5) == q5) ? 0x3C000000u : 0u);                  \
            uint32_t w3 = (((bb & q6) == q6) ? 0x3C00u : 0u) |                     \
                          (((bb & q7) == q7) ? 0x3C000000u : 0u);                  \
            uint32_t dst = (bufbase) + m * 128 + ((kc ^ (m & 7)) << 4);            \
            asm volatile("st.shared.v4.b32 [%0], {%1,%2,%3,%4};"                   \
                         :: "r"(dst), "r"(w0), "r"(w1), "r"(w2), "r"(w3));         \
        }                                                                          \
    } while (0)

    ISSUE_B(0, base);

    // ---- stage this CTA's 128 mask rows coalesced into buf1's space ----
    {
        unsigned int* stage = (unsigned int*)(dynp + BUFB);
        if (kind == 0) {           // u8: 40B/row -> 10 words
            for (int idx = t; idx < 1280; idx += 256)
                stage[idx] = mask_w[(size_t)m0 * 10 + idx];
        } else {                   // 32-bit: 40 words/row
            for (int idx = t; idx < 5120; idx += 256)
                stage[idx] = mask_w[(size_t)m0 * 40 + idx];
        }
        __syncthreads();
        if (t < 128) {
            unsigned long long b = 0ull;
            if (kind == 0) {
                const unsigned int* rp = stage + t * 10;
                #pragma unroll
                for (int wi = 0; wi < 10; ++wi) {
                    unsigned int w = rp[wi];
                    #pragma unroll
                    for (int by = 0; by < 4; ++by)
                        if ((w >> (by * 8)) & 0xFFu) b |= 1ull << (wi * 4 + by);
                }
            } else {
                const unsigned int* rp = stage + t * 40;
                #pragma unroll
                for (int f = 0; f < FF; ++f)
                    if (rp[f]) b |= 1ull << f;
            }
            s_bits[t] = b;
            int cnt = 0;
            unsigned long long x = b;
            while (x) {
                int i = __ffsll((long long)x) - 1;
                x &= x - 1;
                cnt += __popcll(s_avr[i] & b);
            }
            s_scale[t] = (cnt > 0) ? (1.0f / (float)cnt) : 0.0f;
        }
        __syncthreads();
    }

    float acc[2][16][4];
    #pragma unroll
    for (int i = 0; i < 2; ++i)
        #pragma unroll
        for (int j = 0; j < 16; ++j)
            #pragma unroll
            for (int q = 0; q < 4; ++q) acc[i][j][q] = 0.f;

    BUILD_A(0, base);
    asm volatile("cp.async.wait_group 0;" ::: "memory");
    __syncthreads();

    for (int c = 0; c < nch; ++c) {
        uint32_t cur = base + (c & 1) * BUFB;
        if (c + 1 < nch) {
            uint32_t nxt = base + ((c + 1) & 1) * BUFB;
            ISSUE_B(c + 1, nxt);
            BUILD_A(c + 1, nxt);
        }
        uint32_t Ab = cur, Bb = cur + ABYTES;
        #pragma unroll
        for (int ks = 0; ks < 4; ++ks) {
            uint32_t a[2][4];
            #pragma unroll
            for (int mi = 0; mi < 2; ++mi) {
                int arow = wm + mi * 16 + (lane & 7) + ((lane >> 3) & 1) * 8;
                int akc = ks * 2 + (lane >> 4);
                uint32_t ad = Ab + arow * 128 + ((akc ^ (arow & 7)) << 4);
                LDSM4(a[mi][0], a[mi][1], a[mi][2], a[mi][3], ad);
            }
            #pragma unroll
            for (int nb2 = 0; nb2 < 8; ++nb2) {
                int brow = wn + nb2 * 16 + (lane & 7) + (lane >> 4) * 8;
                int bkc = ks * 2 + ((lane >> 3) & 1);
                uint32_t off = brow * 128 + ((bkc ^ (brow & 7)) << 4);
                uint32_t b0, b1, b2, b3;
                LDSM4(b0, b1, b2, b3, Bb + off);
                MMA_F16(acc[0][nb2 * 2 + 0], a[0], b0, b1);
                MMA_F16(acc[1][nb2 * 2 + 0], a[1], b0, b1);
                MMA_F16(acc[0][nb2 * 2 + 1], a[0], b2, b3);
                MMA_F16(acc[1][nb2 * 2 + 1], a[1], b2, b3);
            }
        }
        if (c + 1 < nch) {
            asm volatile("cp.async.wait_group 0;" ::: "memory");
        }
        __syncthreads();
    }

    // ---- epilogue: scale by 1/cnt, add bias, store ----
    #pragma unroll
    for (int mi = 0; mi < 2; ++mi) {
        int rl = wm + mi * 16 + (lane >> 2);
        int row0 = m0 + rl;
        float sc0 = s_scale[rl];
        float sc1 = s_scale[rl + 8];
        #pragma unroll
        for (int ni = 0; ni < 16; ++ni) {
            int col = wn + ni * 8 + 2 * (lane & 3);
            float bv0 = s_bias[col], bv1 = s_bias[col + 1];
            float2 o0, o1;
            o0.x = acc[mi][ni][0] * sc0 + bv0;
            o0.y = acc[mi][ni][1] * sc0 + bv1;
            o1.x = acc[mi][ni][2] * sc1 + bv0;
            o1.y = acc[mi][ni][3] * sc1 + bv1;
            *(float2*)(out + (size_t)row0 * HH + col) = o0;
            *(float2*)(out + (size_t)(row0 + 8) * HH + col) = o1;
        }
    }
}

// ---------------- launch ----------------
extern "C" void kernel_launch(void* const* d_in, const int* in_sizes, int n_in,
                              void* d_out, int out_size) {
    const void* mask = d_in[0];                    // [64,256,40] bool
    const float* E = (const float*)d_in[1];        // [40,40,768] f32
    const void* avail = (const void*)d_in[2];      // [40,40] bool
    const float* W = (const float*)d_in[3];        // [256,768] f32
    const float* bias = (const float*)d_in[4];     // [256] f32
    float* out = (float*)d_out;                    // [64,256,256] f32

    cudaFuncSetAttribute(gemm_kernel, cudaFuncAttributeMaxDynamicSharedMemorySize,
                         DSMEM_BYTES);

    setup_kernel<<<1, 1024>>>((const unsigned int*)mask, in_sizes[0], avail);
    ew_kernel<<<dim3(52, 4), 256>>>(E, W);
    gemm_kernel<<<BT_TOTAL / 128, 256, DSMEM_BYTES>>>((const unsigned int*)mask,
                                                      bias, out);
}

// round 5
// speedup vs baseline: 3.3141x; 1.1713x over previous
#include <cuda_runtime.h>
#include <cuda_fp16.h>
#include <cstdint>

#define FF 40
#define DD 768
#define HH 256
#define MAXP 780           // F*(F-1)/2
#define PPAD 832           // 13*64, >= MAXP, multiple of 64
#define BT_TOTAL (64*256)
#define KC 64

// ---------------- device scratch (no allocations allowed) ----------------
__device__ int g_mask_kind;                     // 0=u8, 1=32-bit (i32/f32)
__device__ int g_P;
__device__ unsigned long long g_pairmask[PPAD]; // compacted; pad = ~0 (never matches)
__device__ int g_pi[MAXP];
__device__ int g_pj[MAXP];
__device__ unsigned long long g_availrow[FF];
__device__ __align__(16) __half g_EWT[HH * PPAD];  // transposed: [h][p], fp16

__device__ __forceinline__ uint32_t smem_u32(const void* p) {
    return (uint32_t)__cvta_generic_to_shared(p);
}

// ---------------- 1) lean setup: dtype detect + pair compaction ----------------
__global__ void __launch_bounds__(256) setup_kernel(const unsigned int* __restrict__ mask_w,
                                                    const void* __restrict__ avail) {
    __shared__ unsigned char flagb[800];
    __shared__ unsigned char pii[800], pjj[800];
    __shared__ unsigned int s_words[25];
    __shared__ int s_woff[25];
    __shared__ int s_P;

    int t = threadIdx.x;

    // detect mask dtype: u8 bools pack random 0/1 bytes -> words outside the set
    int okM = 1;
    for (int i = t; i < 512; i += 256) {
        unsigned int v = mask_w[i];
        okM &= (v == 0u) | (v == 1u) | (v == 0x3F800000u);
    }
    okM = __syncthreads_and(okM);
    if (t == 0) g_mask_kind = okM;

    // detect avail dtype (first 400 words valid for both layouts)
    int okA = 1;
    {
        const unsigned int* aw = (const unsigned int*)avail;
        for (int i = t; i < 400; i += 256) {
            unsigned int v = aw[i];
            okA &= (v == 0u) | (v == 1u) | (v == 0x3F800000u);
        }
    }
    okA = __syncthreads_and(okA);

    // flags, row-parallel: thread i handles row i (j > i)
    if (t < FF) {
        int i = t;
        int base = 39 * i - (i * (i - 1)) / 2;
        unsigned long long rbits = 0ull;
        for (int j = i + 1; j < FF; ++j) {
            int v;
            if (okA) v = ((const unsigned int*)avail)[i * FF + j] != 0u;
            else     v = ((const unsigned char*)avail)[i * FF + j] != 0;
            int idx = base + (j - i - 1);
            flagb[idx] = (unsigned char)v;
            pii[idx] = (unsigned char)i;
            pjj[idx] = (unsigned char)j;
            if (v) rbits |= 1ull << j;
        }
        g_availrow[i] = rbits;
    }
    if (t >= 40 && t < 60) flagb[780 + (t - 40)] = 0;
    __syncthreads();

    // pack flags to 25 ballot words
    if (t < 25) {
        unsigned int wbits = 0;
        #pragma unroll
        for (int q = 0; q < 8; ++q) {
            unsigned int fb = ((const unsigned int*)flagb)[t * 8 + q];
            wbits |= (fb & 1u) << (4 * q)
                   | ((fb >> 8) & 1u) << (4 * q + 1)
                   | ((fb >> 16) & 1u) << (4 * q + 2)
                   | ((fb >> 24) & 1u) << (4 * q + 3);
        }
        s_words[t] = wbits;
    }
    __syncthreads();
    if (t == 0) {
        int s = 0;
        for (int w = 0; w < 25; ++w) { s_woff[w] = s; s += __popc(s_words[w]); }
        s_P = s; g_P = s;
    }
    __syncthreads();

    // scatter compacted pair data
    #pragma unroll
    for (int r = 0; r < 4; ++r) {
        int idx = t + 256 * r;
        if (idx < MAXP && flagb[idx]) {
            int pos = s_woff[idx >> 5] +
                      __popc(s_words[idx >> 5] & ((1u << (idx & 31)) - 1u));
            int i = pii[idx], j = pjj[idx];
            g_pairmask[pos] = (1ull << i) | (1ull << j);
            g_pi[pos] = i;
            g_pj[pos] = j;
        }
    }
    int P = s_P;
    #pragma unroll
    for (int r = 0; r < 4; ++r) {
        int idx = t + 256 * r;
        if (idx < PPAD && idx >= P) g_pairmask[idx] = ~0ull;
    }
}

// ---------------- 2) EWT[h,p] = sum_d E[i_p,j_p,d] * W[h,d]  (fp32 -> fp16) ----------------
// 64-thread blocks, 8p x 32h, 2x2 microtile, register-prefetch pipeline.
// grid (104, 8): blocks beyond nch*64 exit; [P, nch*64) zero-filled.
__global__ void __launch_bounds__(64) ew_kernel(const float* __restrict__ E,
                                                const float* __restrict__ W) {
    int P = g_P;
    int nch = (P + 63) >> 6;
    if (nch < 1) nch = 1;
    int p0 = blockIdx.x * 8;
    if (p0 >= nch * 64) return;
    int h0 = blockIdx.y * 32;
    int t = threadIdx.x;

    if (p0 >= P) {   // pure padding rows needed by gemm: zero-fill (u32 = 2 halves)
        for (int q = t; q < 32 * 4; q += 64) {
            int hcz = q >> 2, pq = q & 3;
            *(unsigned int*)&g_EWT[(h0 + hcz) * PPAD + p0 + pq * 2] = 0u;
        }
        return;
    }

    __shared__ float sE[8][36];
    __shared__ float sW[32][36];
    __shared__ int s_rb[8];

    if (t < 8) {
        int p = p0 + t;
        s_rb[t] = (p < P) ? (g_pi[p] * FF + g_pj[p]) * DD : -1;
    }
    __syncthreads();

    const int erow = t >> 3, ekq = t & 7;       // E load slot (1 float4)
    const int ebase = s_rb[erow];
    const int prow = (t >> 4) * 2;              // 2p
    const int hc = t & 15;                      // 2h: hc, hc+16

    float4 re, rw[4];
    // prefetch chunk 0
    {
        re = make_float4(0.f, 0.f, 0.f, 0.f);
        if (ebase >= 0) re = *(const float4*)(E + ebase + ekq * 4);
        #pragma unroll
        for (int r = 0; r < 4; ++r) {
            int idx = t + 64 * r;
            int row = idx >> 3, kq = idx & 7;
            rw[r] = *(const float4*)(W + (size_t)(h0 + row) * DD + kq * 4);
        }
    }

    float a00 = 0.f, a01 = 0.f, a10 = 0.f, a11 = 0.f;

    for (int c = 0; c < DD / 32; ++c) {
        __syncthreads();
        *(float4*)&sE[erow][ekq * 4] = re;
        #pragma unroll
        for (int r = 0; r < 4; ++r) {
            int idx = t + 64 * r;
            int row = idx >> 3, kq = idx & 7;
            *(float4*)&sW[row][kq * 4] = rw[r];
        }
        __syncthreads();
        if (c + 1 < DD / 32) {
            int k0 = (c + 1) * 32;
            re = make_float4(0.f, 0.f, 0.f, 0.f);
            if (ebase >= 0) re = *(const float4*)(E + ebase + k0 + ekq * 4);
            #pragma unroll
            for (int r = 0; r < 4; ++r) {
                int idx = t + 64 * r;
                int row = idx >> 3, kq = idx & 7;
                rw[r] = *(const float4*)(W + (size_t)(h0 + row) * DD + k0 + kq * 4);
            }
        }
        #pragma unroll
        for (int kk = 0; kk < 32; kk += 4) {
            float4 e0 = *(float4*)&sE[prow][kk];
            float4 e1 = *(float4*)&sE[prow + 1][kk];
            float4 w0 = *(float4*)&sW[hc][kk];
            float4 w1 = *(float4*)&sW[hc + 16][kk];
            a00 += e0.x * w0.x + e0.y * w0.y + e0.z * w0.z + e0.w * w0.w;
            a01 += e0.x * w1.x + e0.y * w1.y + e0.z * w1.z + e0.w * w1.w;
            a10 += e1.x * w0.x + e1.y * w0.y + e1.z * w0.z + e1.w * w0.w;
            a11 += e1.x * w1.x + e1.y * w1.y + e1.z * w1.z + e1.w * w1.w;
        }
    }

    int pA = p0 + prow, pB = pA + 1;
    g_EWT[(h0 + hc) * PPAD + pA]      = __float2half_rn(a00);
    g_EWT[(h0 + hc + 16) * PPAD + pA] = __float2half_rn(a01);
    g_EWT[(h0 + hc) * PPAD + pB]      = __float2half_rn(a10);
    g_EWT[(h0 + hc + 16) * PPAD + pB] = __float2half_rn(a11);
}

// ---------------- 3) mma.sync GEMM: out = (sel @ EW) * (1/cnt) + bias ----------------
// BM=128, BN=256, KC=64; 8 warps as 2m x 4n, warp tile 64m x 64n (B frags reused 4x).
#define ABYTES 16384                 // 128 x 64 fp16
#define BBYTES 32768                 // 256 x 64 fp16
#define BUFB (ABYTES + BBYTES)       // 48 KB
#define DSMEM_BYTES (2 * BUFB + 128)

#define LDSM4(r0, r1, r2, r3, addr) \
    asm volatile("ldmatrix.sync.aligned.m8n8.x4.shared.b16 {%0,%1,%2,%3}, [%4];" \
                 : "=r"(r0), "=r"(r1), "=r"(r2), "=r"(r3) : "r"(addr))

#define MMA_F16(d, a, b0v, b1v) \
    asm volatile("mma.sync.aligned.m16n8k16.row.col.f32.f16.f16.f32 " \
                 "{%0,%1,%2,%3}, {%4,%5,%6,%7}, {%8,%9}, {%0,%1,%2,%3};" \
                 : "+f"((d)[0]), "+f"((d)[1]), "+f"((d)[2]), "+f"((d)[3]) \
                 : "r"((a)[0]), "r"((a)[1]), "r"((a)[2]), "r"((a)[3]), \
                   "r"(b0v), "r"(b1v))

__global__ void __launch_bounds__(256, 1)
gemm_kernel(const unsigned int* __restrict__ mask_w,
            const float* __restrict__ bias, float* __restrict__ out) {
    extern __shared__ char dyn_raw[];
    __shared__ unsigned long long s_pm[PPAD];
    __shared__ unsigned long long s_bits[128];
    __shared__ unsigned long long s_avr[FF];
    __shared__ float s_scale[128];
    __shared__ float s_bias[HH];

    uint32_t raw = smem_u32(dyn_raw);
    uint32_t base = (raw + 127u) & ~127u;
    char* dynp = dyn_raw + (base - raw);

    const int t = threadIdx.x;
    const int lane = t & 31, wid = t >> 5;
    const int wm = (wid & 1) * 64;      // 2 m-groups
    const int wn = (wid >> 1) * 64;     // 4 n-groups
    const int m0 = blockIdx.x * 128;

    for (int i = t; i < PPAD; i += 256) s_pm[i] = g_pairmask[i];
    if (t < FF) s_avr[t] = g_availrow[t];
    s_bias[t] = bias[t];
    int kind = g_mask_kind;
    int P = g_P;
    int nch = (P + KC - 1) / KC;
    if (nch < 1) nch = 1;
    __syncthreads();

    // ---- B chunk via cp.async (fp16), swizzled 16B units ----
    #define ISSUE_B(c, bufbase) do {                                               \
        _Pragma("unroll")                                                          \
        for (int r = 0; r < 8; ++r) {                                              \
            int idx = t + r * 256;                                                 \
            int row = idx >> 3, kc = idx & 7;                                      \
            const __half* src = g_EWT + (size_t)row * PPAD + (c) * KC + kc * 8;    \
            uint32_t dst = (bufbase) + ABYTES + row * 128 + ((kc ^ (row & 7)) << 4); \
            asm volatile("cp.async.cg.shared.global [%0], [%1], 16;"               \
                         :: "r"(dst), "l"(src));                                   \
        }                                                                          \
        asm volatile("cp.async.commit_group;" ::: "memory");                       \
    } while (0)

    // ---- A (sel, fp16 1.0 = 0x3C00) built from bitmasks ----
    #define BUILD_A(c, bufbase) do {                                               \
        _Pragma("unroll")                                                          \
        for (int r = 0; r < 4; ++r) {                                              \
            int idx = t + r * 256;                                                 \
            int m = idx >> 3, kc = idx & 7;                                        \
            unsigned long long bb = s_bits[m];                                     \
            int pb = (c) * KC + kc * 8;                                            \
            unsigned long long q0 = s_pm[pb+0], q1 = s_pm[pb+1];                   \
            unsigned long long q2 = s_pm[pb+2], q3 = s_pm[pb+3];                   \
            unsigned long long q4 = s_pm[pb+4], q5 = s_pm[pb+5];                   \
            unsigned long long q6 = s_pm[pb+6], q7 = s_pm[pb+7];                   \
            uint32_t w0 = (((bb & q0) == q0) ? 0x3C00u : 0u) |                     \
                          (((bb & q1) == q1) ? 0x3C000000u : 0u);                  \
            uint32_t w1 = (((bb & q2) == q2) ? 0x3C00u : 0u) |                     \
                          (((bb & q3) == q3) ? 0x3C000000u : 0u);                  \
            uint32_t w2 = (((bb & q4) == q4) ? 0x3C00u : 0u) |                     \
                          (((bb & q5) == q5) ? 0x3C000000u : 0u);                  \
            uint32_t w3 = (((bb & q6) == q6) ? 0x3C00u : 0u) |                     \
                          (((bb & q7) == q7) ? 0x3C000000u : 0u);                  \
            uint32_t dst = (bufbase) + m * 128 + ((kc ^ (m & 7)) << 4);            \
            asm volatile("st.shared.v4.b32 [%0], {%1,%2,%3,%4};"                   \
                         :: "r"(dst), "r"(w0), "r"(w1), "r"(w2), "r"(w3));         \
        }                                                                          \
    } while (0)

    ISSUE_B(0, base);

    // ---- stage this CTA's 128 mask rows coalesced, build bits + 1/cnt ----
    {
        unsigned int* stage = (unsigned int*)(dynp + BUFB);
        if (kind == 0) {           // u8: 40B/row -> 10 words
            for (int idx = t; idx < 1280; idx += 256)
                stage[idx] = mask_w[(size_t)m0 * 10 + idx];
        } else {                   // 32-bit: 40 words/row
            for (int idx = t; idx < 5120; idx += 256)
                stage[idx] = mask_w[(size_t)m0 * 40 + idx];
        }
        __syncthreads();
        if (t < 128) {
            unsigned long long b = 0ull;
            if (kind == 0) {
                const unsigned int* rp = stage + t * 10;
                #pragma unroll
                for (int wi = 0; wi < 10; ++wi) {
                    unsigned int w = rp[wi];
                    #pragma unroll
                    for (int by = 0; by < 4; ++by)
                        if ((w >> (by * 8)) & 0xFFu) b |= 1ull << (wi * 4 + by);
                }
            } else {
                const unsigned int* rp = stage + t * 40;
                #pragma unroll
                for (int f = 0; f < FF; ++f)
                    if (rp[f]) b |= 1ull << f;
            }
            s_bits[t] = b;
            int cnt = 0;
            unsigned long long x = b;
            while (x) {
                int i = __ffsll((long long)x) - 1;
                x &= x - 1;
                cnt += __popcll(s_avr[i] & b);
            }
            s_scale[t] = (cnt > 0) ? (1.0f / (float)cnt) : 0.0f;
        }
        __syncthreads();
    }

    float acc[4][8][4];
    #pragma unroll
    for (int i = 0; i < 4; ++i)
        #pragma unroll
        for (int j = 0; j < 8; ++j)
            #pragma unroll
            for (int q = 0; q < 4; ++q) acc[i][j][q] = 0.f;

    BUILD_A(0, base);
    asm volatile("cp.async.wait_group 0;" ::: "memory");
    __syncthreads();

    for (int c = 0; c < nch; ++c) {
        uint32_t cur = base + (c & 1) * BUFB;
        if (c + 1 < nch) {
            uint32_t nxt = base + ((c + 1) & 1) * BUFB;
            ISSUE_B(c + 1, nxt);
            BUILD_A(c + 1, nxt);
        }
        uint32_t Ab = cur, Bb = cur + ABYTES;
        #pragma unroll
        for (int ks = 0; ks < 4; ++ks) {
            uint32_t a[4][4];
            #pragma unroll
            for (int mi = 0; mi < 4; ++mi) {
                int arow = wm + mi * 16 + (lane & 7) + ((lane >> 3) & 1) * 8;
                int akc = ks * 2 + (lane >> 4);
                uint32_t ad = Ab + arow * 128 + ((akc ^ (arow & 7)) << 4);
                LDSM4(a[mi][0], a[mi][1], a[mi][2], a[mi][3], ad);
            }
            #pragma unroll
            for (int nb2 = 0; nb2 < 4; ++nb2) {
                int brow = wn + nb2 * 16 + (lane & 7) + (lane >> 4) * 8;
                int bkc = ks * 2 + ((lane >> 3) & 1);
                uint32_t off = brow * 128 + ((bkc ^ (brow & 7)) << 4);
                uint32_t b0, b1, b2, b3;
                LDSM4(b0, b1, b2, b3, Bb + off);
                #pragma unroll
                for (int mi = 0; mi < 4; ++mi) {
                    MMA_F16(acc[mi][nb2 * 2 + 0], a[mi], b0, b1);
                    MMA_F16(acc[mi][nb2 * 2 + 1], a[mi], b2, b3);
                }
            }
        }
        if (c + 1 < nch) {
            asm volatile("cp.async.wait_group 0;" ::: "memory");
        }
        __syncthreads();
    }

    // ---- epilogue: scale by 1/cnt, add bias, store ----
    #pragma unroll
    for (int mi = 0; mi < 4; ++mi) {
        int rl = wm + mi * 16 + (lane >> 2);
        int row0 = m0 + rl;
        float sc0 = s_scale[rl];
        float sc1 = s_scale[rl + 8];
        #pragma unroll
        for (int nf = 0; nf < 8; ++nf) {
            int col = wn + (nf >> 1) * 16 + (nf & 1) * 8 + 2 * (lane & 3);
            float bv0 = s_bias[col], bv1 = s_bias[col + 1];
            float2 o0, o1;
            o0.x = acc[mi][nf][0] * sc0 + bv0;
            o0.y = acc[mi][nf][1] * sc0 + bv1;
            o1.x = acc[mi][nf][2] * sc1 + bv0;
            o1.y = acc[mi][nf][3] * sc1 + bv1;
            *(float2*)(out + (size_t)row0 * HH + col) = o0;
            *(float2*)(out + (size_t)(row0 + 8) * HH + col) = o1;
        }
    }
}

// ---------------- launch ----------------
extern "C" void kernel_launch(void* const* d_in, const int* in_sizes, int n_in,
                              void* d_out, int out_size) {
    const void* mask = d_in[0];                    // [64,256,40] bool
    const float* E = (const float*)d_in[1];        // [40,40,768] f32
    const void* avail = (const void*)d_in[2];      // [40,40] bool
    const float* W = (const float*)d_in[3];        // [256,768] f32
    const float* bias = (const float*)d_in[4];     // [256] f32
    float* out = (float*)d_out;                    // [64,256,256] f32

    cudaFuncSetAttribute(gemm_kernel, cudaFuncAttributeMaxDynamicSharedMemorySize,
                         DSMEM_BYTES);

    setup_kernel<<<1, 256>>>((const unsigned int*)mask, avail);
    ew_kernel<<<dim3(PPAD / 8, 8), 64>>>(E, W);
    gemm_kernel<<<BT_TOTAL / 128, 256, DSMEM_BYTES>>>((const unsigned int*)mask,
                                                      bias, out);
}